// round 9
// baseline (speedup 1.0000x reference)
#include <cuda_runtime.h>
#include <cuda_bf16.h>

// BSplineLoss on GB300 (sm_103a). Round 8/9: SoA shared layout, register-cached
// knots, fused deterministic final reduction (single launch).
//
// Layout: seq[B][64][3] f32, col0 = knots (strictly increasing), col1..2 = coeffs.
//   kf = [0,0,0,0, knots...] (68), t_i = (i/19)*knots[60]
//   j  = #{ knots[0..59] <= t };  control points v[j..j+3]; cubic De Boor.
// loss = sum over (B,20,2) of (pred-true)^2 / (B*20)

static constexpr int B_ROWS       = 65536;
static constexpr int ROWS_PER_BLK = 16;
static constexpr int THREADS      = ROWS_PER_BLK * 20;     // 320
static constexpr int NUM_BLOCKS   = B_ROWS / ROWS_PER_BLK; // 4096
static constexpr int SLOTS        = ROWS_PER_BLK * 2;      // 32 (row, tensor)
static constexpr int KF_STRIDE    = 72;   // floats per slot (68 used); %32==8 shift
static constexpr int CO_STRIDE    = 66;   // float2 per slot (64 used); 132 floats %32==4
static constexpr float INV_COUNT  = 1.0f / (65536.0f * 20.0f);

__device__ float g_partial[NUM_BLOCKS];
__device__ unsigned int g_count;   // zero-init; reset by last block each run

__device__ __forceinline__ float alpha_f(float t, float ki, float kj) {
    const float d = kj - ki;
    return (d != 0.0f) ? __fdividef(t - ki, d) : 0.0f;
}

__device__ __forceinline__ void eval_spline(const float* __restrict__ kf,
                                            const float2* __restrict__ co,
                                            int i, float& ox, float& oy) {
    const float high = kf[64];                  // knots[60]
    const float t = (float)i * (1.0f / 19.0f) * high;

    // j = count of knots[0..59] <= t  (knots[n] = kf[4+n])
    int lo = 0, hi = 60;
    while (lo < hi) {
        int mid = (lo + hi) >> 1;
        bool le = (kf[4 + mid] <= t);
        lo = le ? (mid + 1) : lo;
        hi = le ? hi : mid;
    }
    const int j = lo;                           // 0..60

    // Register-cache the only knots the recurrence needs: kf[j+1..j+6]
    const float K1 = kf[j + 1], K2 = kf[j + 2], K3 = kf[j + 3];
    const float K4 = kf[j + 4], K5 = kf[j + 5], K6 = kf[j + 6];

    const float2 c0 = co[j], c1 = co[j + 1], c2 = co[j + 2], c3 = co[j + 3];
    float px0 = c0.x, px1 = c1.x, px2 = c2.x, px3 = c3.x;
    float py0 = c0.y, py1 = c1.y, py2 = c2.y, py3 = c3.y;
    float pw0 = 1.0f, pw1 = 1.0f, pw2 = 1.0f, pw3 = 1.0f;

    float a, b;
    // level 1: k = 3,2,1
    a = alpha_f(t, K3, K6); b = 1.0f - a;
    px3 = b * px2 + a * px3; py3 = b * py2 + a * py3; pw3 = b * pw2 + a * pw3;
    a = alpha_f(t, K2, K5); b = 1.0f - a;
    px2 = b * px1 + a * px2; py2 = b * py1 + a * py2; pw2 = b * pw1 + a * pw2;
    a = alpha_f(t, K1, K4); b = 1.0f - a;
    px1 = b * px0 + a * px1; py1 = b * py0 + a * py1; pw1 = b * pw0 + a * pw1;
    // level 2: k = 3,2
    a = alpha_f(t, K3, K5); b = 1.0f - a;
    px3 = b * px2 + a * px3; py3 = b * py2 + a * py3; pw3 = b * pw2 + a * pw3;
    a = alpha_f(t, K2, K4); b = 1.0f - a;
    px2 = b * px1 + a * px2; py2 = b * py1 + a * py2; pw2 = b * pw1 + a * pw2;
    // level 3: k = 3
    a = alpha_f(t, K3, K4); b = 1.0f - a;
    px3 = b * px2 + a * px3; py3 = b * py2 + a * py3; pw3 = b * pw2 + a * pw3;

    const float rw = __fdividef(1.0f, pw3);
    ox = px3 * rw;
    oy = py3 * rw;
}

__global__ __launch_bounds__(THREADS)
void bspline_loss_kernel(const float* __restrict__ pred,
                         const float* __restrict__ truth,
                         float* __restrict__ out) {
    __shared__ float  kf_sh[SLOTS * KF_STRIDE];          // 9216 B
    __shared__ float2 co_sh[SLOTS * CO_STRIDE];          // 16896 B
    __shared__ float  wsum[THREADS / 32];
    __shared__ int    is_last;

    const int tid = threadIdx.x;
    const int rowBase = blockIdx.x * ROWS_PER_BLK;

    // Zero the 4 leading kf entries of every slot
    if (tid < SLOTS * 4) {
        int slot = tid >> 2, m = tid & 3;
        kf_sh[slot * KF_STRIDE + m] = 0.0f;
    }

    // Coalesced scalar staging with SoA transpose.
    // idx -> r (row), tens (0 pred / 1 true), e (0..191); e = 3n + c
    {
        float* co_f = (float*)co_sh;
        for (int idx = tid; idx < ROWS_PER_BLK * 2 * 192; idx += THREADS) {
            int r    = idx / 384;
            int rem  = idx - r * 384;
            int tens = rem / 192;
            int e    = rem - tens * 192;
            int n    = e / 3;
            int c    = e - n * 3;
            const float* src = tens ? truth : pred;
            float v = src[(size_t)(rowBase + r) * 192 + e];
            int slot = r * 2 + tens;
            if (c == 0) kf_sh[slot * KF_STRIDE + 4 + n] = v;
            else        co_f[slot * (CO_STRIDE * 2) + 2 * n + (c - 1)] = v;
        }
    }
    __syncthreads();

    const int r = tid / 20;       // local row
    const int i = tid - r * 20;   // sample index
    const int slot = r * 2;

    float pxv, pyv, tx, ty;
    eval_spline(kf_sh + slot * KF_STRIDE,       co_sh + slot * CO_STRIDE,       i, pxv, pyv);
    eval_spline(kf_sh + (slot + 1) * KF_STRIDE, co_sh + (slot + 1) * CO_STRIDE, i, tx, ty);
    float dx = pxv - tx;
    float dy = pyv - ty;
    float acc = dx * dx + dy * dy;

#pragma unroll
    for (int o = 16; o > 0; o >>= 1)
        acc += __shfl_down_sync(0xffffffffu, acc, o);
    if ((tid & 31) == 0) wsum[tid >> 5] = acc;
    __syncthreads();

    if (tid == 0) {
        float ssum = 0.0f;
#pragma unroll
        for (int w = 0; w < THREADS / 32; ++w) ssum += wsum[w];
        g_partial[blockIdx.x] = ssum;           // non-atomic: deterministic
        __threadfence();
        unsigned int ticket = atomicAdd(&g_count, 1u);
        is_last = (ticket == NUM_BLOCKS - 1);
    }
    __syncthreads();

    if (is_last) {
        // Deterministic final reduction: fixed index order, fixed tree.
        float acc2 = 0.0f;
#pragma unroll
        for (int k = 0; k < 13; ++k) {          // ceil(4096/320)
            int idx = tid + k * THREADS;
            if (idx < NUM_BLOCKS) acc2 += g_partial[idx];
        }
#pragma unroll
        for (int o = 16; o > 0; o >>= 1)
            acc2 += __shfl_down_sync(0xffffffffu, acc2, o);
        if ((tid & 31) == 0) wsum[tid >> 5] = acc2;
        __syncthreads();
        if (tid == 0) {
            float ssum = 0.0f;
#pragma unroll
            for (int w = 0; w < THREADS / 32; ++w) ssum += wsum[w];
            out[0] = ssum * INV_COUNT;
            g_count = 0;                        // reset for next replay
        }
    }
}

extern "C" void kernel_launch(void* const* d_in, const int* in_sizes, int n_in,
                              void* d_out, int out_size) {
    const float* pred  = (const float*)d_in[0];
    const float* truth = (const float*)d_in[1];
    // d_in[2] (true_masks) ignored: reference rebuilds an all-ones mask.
    float* out = (float*)d_out;
    bspline_loss_kernel<<<NUM_BLOCKS, THREADS>>>(pred, truth, out);
}

// round 15
// speedup vs baseline: 2.6617x; 2.6617x over previous
#include <cuda_runtime.h>
#include <cuda_bf16.h>

// BSplineLoss on GB300 (sm_103a). Round 10-15: SoA shared + register-cached
// knots (kept from R9) with HOISTED staging index math (fix for R9's ALU
// explosion: 72.5% alu pipe from per-element div/mod). THREADS=384 = one row
// (2x192) so all staging div/mod is loop-invariant; 16 unrolled LDG+STS/thread.
//
// Layout: seq[B][64][3] f32, col0 = knots (strictly increasing), col1..2 = coeffs.
//   kf = [0,0,0,0, knots...] (68), t_i = (i/19)*knots[60]
//   j  = #{ knots[0..59] <= t };  control points v[j..j+3]; cubic De Boor.
// loss = sum over (B,20,2) of (pred-true)^2 / (B*20)

static constexpr int B_ROWS       = 65536;
static constexpr int ROWS_PER_BLK = 16;
static constexpr int THREADS      = 384;                   // = 2 tensors * 192 floats
static constexpr int EVAL_THREADS = ROWS_PER_BLK * 20;     // 320 active in eval
static constexpr int NUM_BLOCKS   = B_ROWS / ROWS_PER_BLK; // 4096
static constexpr int SLOTS        = ROWS_PER_BLK * 2;      // 32 (row, tensor)
static constexpr int KF_STRIDE    = 72;   // floats per slot (68 used); %32==8 shift
static constexpr int CO_STRIDE    = 66;   // float2 per slot (64 used)
static constexpr int NWARPS       = THREADS / 32;          // 12
static constexpr float INV_COUNT  = 1.0f / (65536.0f * 20.0f);

__device__ float g_partial[NUM_BLOCKS];
__device__ unsigned int g_count;   // zero-init; reset by last block each run

__device__ __forceinline__ float alpha_f(float t, float ki, float kj) {
    const float d = kj - ki;
    return (d != 0.0f) ? __fdividef(t - ki, d) : 0.0f;
}

__device__ __forceinline__ void eval_spline(const float* __restrict__ kf,
                                            const float2* __restrict__ co,
                                            int i, float& ox, float& oy) {
    const float high = kf[64];                  // knots[60]
    const float t = (float)i * (1.0f / 19.0f) * high;

    // j = count of knots[0..59] <= t  (knots[n] = kf[4+n])
    int lo = 0, hi = 60;
    while (lo < hi) {
        int mid = (lo + hi) >> 1;
        bool le = (kf[4 + mid] <= t);
        lo = le ? (mid + 1) : lo;
        hi = le ? hi : mid;
    }
    const int j = lo;                           // 0..60

    // Register-cache the only knots the recurrence needs: kf[j+1..j+6]
    const float K1 = kf[j + 1], K2 = kf[j + 2], K3 = kf[j + 3];
    const float K4 = kf[j + 4], K5 = kf[j + 5], K6 = kf[j + 6];

    const float2 c0 = co[j], c1 = co[j + 1], c2 = co[j + 2], c3 = co[j + 3];
    float px0 = c0.x, px1 = c1.x, px2 = c2.x, px3 = c3.x;
    float py0 = c0.y, py1 = c1.y, py2 = c2.y, py3 = c3.y;
    float pw0 = 1.0f, pw1 = 1.0f, pw2 = 1.0f, pw3 = 1.0f;

    float a, b;
    // level 1: k = 3,2,1
    a = alpha_f(t, K3, K6); b = 1.0f - a;
    px3 = b * px2 + a * px3; py3 = b * py2 + a * py3; pw3 = b * pw2 + a * pw3;
    a = alpha_f(t, K2, K5); b = 1.0f - a;
    px2 = b * px1 + a * px2; py2 = b * py1 + a * py2; pw2 = b * pw1 + a * pw2;
    a = alpha_f(t, K1, K4); b = 1.0f - a;
    px1 = b * px0 + a * px1; py1 = b * py0 + a * py1; pw1 = b * pw0 + a * pw1;
    // level 2: k = 3,2
    a = alpha_f(t, K3, K5); b = 1.0f - a;
    px3 = b * px2 + a * px3; py3 = b * py2 + a * py3; pw3 = b * pw2 + a * pw3;
    a = alpha_f(t, K2, K4); b = 1.0f - a;
    px2 = b * px1 + a * px2; py2 = b * py1 + a * py2; pw2 = b * pw1 + a * pw2;
    // level 3: k = 3
    a = alpha_f(t, K3, K4); b = 1.0f - a;
    px3 = b * px2 + a * px3; py3 = b * py2 + a * py3; pw3 = b * pw2 + a * pw3;

    const float rw = __fdividef(1.0f, pw3);
    ox = px3 * rw;
    oy = py3 * rw;
}

__global__ __launch_bounds__(THREADS)
void bspline_loss_kernel(const float* __restrict__ pred,
                         const float* __restrict__ truth,
                         float* __restrict__ out) {
    __shared__ float  kf_sh[SLOTS * KF_STRIDE];          // 9216 B
    __shared__ float2 co_sh[SLOTS * CO_STRIDE];          // 16896 B
    __shared__ float  wsum[NWARPS];
    __shared__ int    is_last;

    const int tid = threadIdx.x;
    const int rowBase = blockIdx.x * ROWS_PER_BLK;

    // Zero the 4 leading kf entries of every slot
    if (tid < SLOTS * 4) {
        int slot = tid >> 2, m = tid & 3;
        kf_sh[slot * KF_STRIDE + m] = 0.0f;
    }

    // Staging with ALL index math hoisted: tid encodes (tens, e) once;
    // the k-loop walks rows (r = k exactly, since THREADS == 2*192).
    {
        float* co_f = (float*)co_sh;
        const int  tens = tid / 192;             // 0 pred / 1 true (hoisted)
        const int  e    = tid - tens * 192;      // 0..191          (hoisted)
        const int  n    = e / 3;                 // knot/coeff idx  (hoisted)
        const int  c    = e - n * 3;             // component       (hoisted)
        const float* src = tens ? truth : pred;
        const size_t gbase = (size_t)rowBase * 192 + e;
        // Destination bases for k=0; per-k increments are compile-time consts.
        const bool  is_knot = (c == 0);
        const int   kf_base = tens * KF_STRIDE + 4 + n;
        const int   co_base = tens * (CO_STRIDE * 2) + 2 * n + (c - 1);
#pragma unroll
        for (int k = 0; k < ROWS_PER_BLK; ++k) {
            float v = src[gbase + (size_t)k * 192];
            int slot2 = k * 2;                   // slot = k*2 + tens folded into bases
            if (is_knot) kf_sh[slot2 * KF_STRIDE + kf_base] = v;
            else         co_f [slot2 * (CO_STRIDE * 2) + co_base] = v;
        }
    }
    __syncthreads();

    float acc = 0.0f;
    if (tid < EVAL_THREADS) {
        const int r = tid / 20;       // local row
        const int i = tid - r * 20;   // sample index
        const int slot = r * 2;

        float pxv, pyv, tx, ty;
        eval_spline(kf_sh + slot * KF_STRIDE,       co_sh + slot * CO_STRIDE,       i, pxv, pyv);
        eval_spline(kf_sh + (slot + 1) * KF_STRIDE, co_sh + (slot + 1) * CO_STRIDE, i, tx, ty);
        float dx = pxv - tx;
        float dy = pyv - ty;
        acc = dx * dx + dy * dy;
    }

#pragma unroll
    for (int o = 16; o > 0; o >>= 1)
        acc += __shfl_down_sync(0xffffffffu, acc, o);
    if ((tid & 31) == 0) wsum[tid >> 5] = acc;
    __syncthreads();

    if (tid == 0) {
        float ssum = 0.0f;
#pragma unroll
        for (int w = 0; w < NWARPS; ++w) ssum += wsum[w];
        g_partial[blockIdx.x] = ssum;           // non-atomic: deterministic
        __threadfence();
        unsigned int ticket = atomicAdd(&g_count, 1u);
        is_last = (ticket == NUM_BLOCKS - 1);
    }
    __syncthreads();

    if (is_last) {
        // Deterministic final reduction: fixed index order, fixed tree.
        float acc2 = 0.0f;
#pragma unroll
        for (int k = 0; k < 11; ++k) {          // ceil(4096/384)
            int idx = tid + k * THREADS;
            if (idx < NUM_BLOCKS) acc2 += g_partial[idx];
        }
#pragma unroll
        for (int o = 16; o > 0; o >>= 1)
            acc2 += __shfl_down_sync(0xffffffffu, acc2, o);
        if ((tid & 31) == 0) wsum[tid >> 5] = acc2;
        __syncthreads();
        if (tid == 0) {
            float ssum = 0.0f;
#pragma unroll
            for (int w = 0; w < NWARPS; ++w) ssum += wsum[w];
            out[0] = ssum * INV_COUNT;
            g_count = 0;                        // reset for next replay
        }
    }
}

extern "C" void kernel_launch(void* const* d_in, const int* in_sizes, int n_in,
                              void* d_out, int out_size) {
    const float* pred  = (const float*)d_in[0];
    const float* truth = (const float*)d_in[1];
    // d_in[2] (true_masks) ignored: reference rebuilds an all-ones mask.
    float* out = (float*)d_out;
    bspline_loss_kernel<<<NUM_BLOCKS, THREADS>>>(pred, truth, out);
}